// round 8
// baseline (speedup 1.0000x reference)
#include <cuda_runtime.h>
#include <cuda_bf16.h>

// DenseRadiusGraph R7: cell list (x:10 cells side 10, y/z:5 cells side 20),
// fused single-kernel build with warp-shuffle scan, warp-per-query search
// with u64-packed (dist,idx) keys for the distributed top-K.
//
// Numerics: selection/ordering uses the reference's GEMM-form distance with
// plain fp32 rounding (no FMA, fixed association); ties broken by (dist,
// index) lexicographic == top_k lowest-index-first, via monotone u64 keys
// (nonneg float bits are order-isomorphic; idx in low 32). Independent of the
// nondeterministic scatter order. w = direct-form distance, non-FMA.

#define BGR   16
#define NGR   2048
#define KNB   32
#define NCX   10
#define NCYZ  5
#define NCELL (NCX * NCYZ * NCYZ)   // 250
#define TPB   256
#define QPB   (TPB / 32)
#define BT    512                    // build threads per block
#define NPT   (NGR / BT)             // 4 nodes per build thread

typedef unsigned long long u64;

// Scratch (device globals: no allocation allowed).
__device__ float4 g_sorted[BGR * NGR];          // cell-sorted {x,y,z,sq}
__device__ int    g_sidx[BGR * NGR];            // original local index
__device__ int    g_cellstart[BGR * NCELL + 1]; // absolute offsets (+sentinel)

__device__ __forceinline__ int clamp_x(float v) {
    int c = __float2int_rd(v * 0.1f);            // /10
    return min(NCX - 1, max(0, c));
}
__device__ __forceinline__ int clamp_yz(float v) {
    int c = __float2int_rd(v * 0.05f);           // /20
    return min(NCYZ - 1, max(0, c));
}

// ---- fused build: one CTA per graph, warp-shuffle scan -------------------

__global__ __launch_bounds__(BT) void k_build(const float* __restrict__ pos) {
    __shared__ int s_cnt[NCELL];
    __shared__ int s_woff[BT / 32];   // 16 per-warp scan offsets
    __shared__ int s_cur[NCELL];

    const int b    = blockIdx.x;
    const int t    = threadIdx.x;
    const int warp = t >> 5;
    const int lane = t & 31;
    const unsigned FULL = 0xffffffffu;
    const float* gp = pos + (size_t)b * NGR * 3;

    for (int i = t; i < NCELL; i += BT) s_cnt[i] = 0;
    __syncthreads();

    // Phase 1: load nodes, compute cell ids, shared histogram.
    float px[NPT], py[NPT], pz[NPT];
    int   cid[NPT];
    #pragma unroll
    for (int k = 0; k < NPT; ++k) {
        int n = t + k * BT;
        px[k] = gp[3 * n + 0];
        py[k] = gp[3 * n + 1];
        pz[k] = gp[3 * n + 2];
        cid[k] = (clamp_yz(pz[k]) * NCYZ + clamp_yz(py[k])) * NCX + clamp_x(px[k]);
        atomicAdd(&s_cnt[cid[k]], 1);
    }
    __syncthreads();

    // Phase 2: exclusive scan of 250 counters (warp shfl scans + 1 top scan).
    int v = (t < NCELL) ? s_cnt[t] : 0;
    int incl = v;
    #pragma unroll
    for (int d = 1; d < 32; d <<= 1) {
        int u = __shfl_up_sync(FULL, incl, d);
        if (lane >= d) incl += u;
    }
    if (lane == 31) s_woff[warp] = incl;
    __syncthreads();
    if (warp == 0 && lane < BT / 32) {
        int w = s_woff[lane];
        int iw = w;
        #pragma unroll
        for (int d = 1; d < BT / 32; d <<= 1) {
            int u = __shfl_up_sync(0x0000ffffu, iw, d);
            if (lane >= d) iw += u;
        }
        s_woff[lane] = iw - w;   // exclusive warp offset
    }
    __syncthreads();
    if (t < NCELL) {
        int excl = incl - v + s_woff[warp];
        s_cur[t] = excl;
        g_cellstart[b * NCELL + t] = b * NGR + excl;
    }
    if (b == 0 && t == 0) g_cellstart[BGR * NCELL] = BGR * NGR;
    __syncthreads();

    // Phase 3: scatter via shared atomic cursors.
    const int base = b * NGR;
    #pragma unroll
    for (int k = 0; k < NPT; ++k) {
        int slot = base + atomicAdd(&s_cur[cid[k]], 1);
        float sq = __fadd_rn(__fadd_rn(__fmul_rn(px[k], px[k]),
                                       __fmul_rn(py[k], py[k])),
                             __fmul_rn(pz[k], pz[k]));
        g_sorted[slot] = make_float4(px[k], py[k], pz[k], sq);
        g_sidx[slot]   = t + k * BT;
    }
}

// ---- search: one warp per query, u64-key distributed top-K ---------------

__global__ __launch_bounds__(TPB) void k_search(
    const float* __restrict__ pos, float* __restrict__ out, int M)
{
    const int b    = blockIdx.y;
    const int warp = threadIdx.x >> 5;
    const int lane = threadIdx.x & 31;
    const unsigned FULL = 0xffffffffu;

    const int n = blockIdx.x * QPB + warp;
    const float* gp = pos + (size_t)b * NGR * 3;
    float qx = gp[3 * n + 0], qy = gp[3 * n + 1], qz = gp[3 * n + 2];
    float qw = __fadd_rn(__fadd_rn(__fmul_rn(qx, qx), __fmul_rn(qy, qy)),
                         __fmul_rn(qz, qz));

    const int x0 = clamp_x(qx - 10.01f),  x1 = clamp_x(qx + 10.01f);
    const int y0 = clamp_yz(qy - 10.01f), y1 = clamp_yz(qy + 10.01f);
    const int z0 = clamp_yz(qz - 10.01f), z1 = clamp_yz(qz + 10.01f);

    // Lane l holds the l-th smallest key. Invalid sentinel: INF bits + all-one
    // low word (sorts after every real key; real dist<=10 => high<0x41200001).
    const u64 KINF = 0x7f800000ffffffffULL;
    u64 kk = KINF;

    for (int cz = z0; cz <= z1; ++cz) {
        for (int cy = y0; cy <= y1; ++cy) {
            int rowbase = b * NCELL + (cz * NCYZ + cy) * NCX;
            int s = g_cellstart[rowbase + x0];
            int e = g_cellstart[rowbase + x1 + 1];  // contiguous x-run
            for (int t0 = s; t0 < e; t0 += 32) {
                int  t   = t0 + lane;
                bool act = t < e;
                float4 c = act ? g_sorted[t] : make_float4(0.f, 0.f, 0.f, 1e30f);
                // Reference-rounded GEMM-form d2 (no FMA, fixed association).
                float m1 = __fmul_rn(qx, c.x);
                float m2 = __fmul_rn(qy, c.y);
                float m3 = __fmul_rn(qz, c.z);
                float dote = __fadd_rn(__fadd_rn(m1, m2), m3);
                float tt   = __fadd_rn(qw, c.w);
                float d2   = __fsub_rn(tt, __fmul_rn(2.0f, dote));
                u64  mykey = KINF;
                bool hit   = false;
                if (act && d2 <= 100.001f) {
                    float de = __fsqrt_rn(fmaxf(d2, 0.0f));
                    int   jl = g_sidx[t];
                    if (de <= 10.0f && jl != n) {
                        mykey = ((u64)__float_as_uint(de) << 32) | (unsigned)jl;
                        hit = true;
                    }
                }
                unsigned emask = __ballot_sync(FULL, hit);
                while (emask) {
                    int src = __ffs(emask) - 1;
                    emask &= emask - 1;
                    u64 nk = __shfl_sync(FULL, mykey, src);
                    int p  = __popc(__ballot_sync(FULL, kk < nk));
                    u64 sk = __shfl_up_sync(FULL, kk, 1);
                    if (p < 32) {
                        if (lane == p)     kk = nk;
                        else if (lane > p) kk = sk;
                    }
                }
            }
        }
    }

    // Emit: lane l writes slot l. Invalid -> zeros.
    const int  g    = b * NGR + n;
    const long base = (long)g * KNB;
    float* rowp = out;
    float* colp = out + (long)M;
    float* wp   = out + 2L * (long)M;
    float* vp   = out + 3L * (long)M;

    float rv = 0.0f, cv = 0.0f, wv = 0.0f, vv = 0.0f;
    if (kk != KINF) {
        int ki = (int)(unsigned)(kk & 0xffffffffu);
        float cxp = gp[3 * ki + 0], cyp = gp[3 * ki + 1], czp = gp[3 * ki + 2];
        float dx = __fsub_rn(qx, cxp);
        float dy = __fsub_rn(qy, cyp);
        float dz = __fsub_rn(qz, czp);
        float ss = __fadd_rn(__fadd_rn(__fmul_rn(dx, dx), __fmul_rn(dy, dy)),
                             __fmul_rn(dz, dz));
        wv = __fsqrt_rn(ss);
        rv = (float)g;
        cv = (float)(b * NGR + ki);
        vv = 1.0f;
    }
    rowp[base + lane] = rv;
    colp[base + lane] = cv;
    wp[base + lane]   = wv;
    vp[base + lane]   = vv;
}

// ---- launch --------------------------------------------------------------

extern "C" void kernel_launch(void* const* d_in, const int* in_sizes, int n_in,
                              void* d_out, int out_size) {
    const float* pos = (const float*)d_in[0];
    (void)in_sizes; (void)n_in;
    float* out = (float*)d_out;
    int M = out_size / 4;

    k_build<<<BGR, BT>>>(pos);
    dim3 grid(NGR / QPB, BGR, 1);
    k_search<<<grid, TPB>>>(pos, out, M);
}

// round 9
// speedup vs baseline: 1.0092x; 1.0092x over previous
#include <cuda_runtime.h>
#include <cuda_bf16.h>

// DenseRadiusGraph R8 = R7's fast warp-scan build + R6's 32-bit search
// (reverting R7's u64-key top-K, which cost 7 regs and 18% occupancy for
// zero instruction saving: shfl.b64 == 2x shfl.b32).
//
// Cells: x side 10 (10 cells), y/z side 20 (5 cells) => 250 cells/graph.
// Numerics: selection/ordering uses the reference's GEMM-form distance with
// plain fp32 rounding (no FMA, fixed association); ties broken
// lexicographically by (dist, index) == top_k lowest-index-first, independent
// of the nondeterministic scatter order. w = direct-form distance, non-FMA.

#define BGR   16
#define NGR   2048
#define KNB   32
#define NCX   10
#define NCYZ  5
#define NCELL (NCX * NCYZ * NCYZ)   // 250
#define TPB   256
#define QPB   (TPB / 32)
#define BT    512                    // build threads per block
#define NPT   (NGR / BT)             // 4 nodes per build thread

// Scratch (device globals: no allocation allowed).
__device__ float4 g_sorted[BGR * NGR];          // cell-sorted {x,y,z,sq}
__device__ int    g_sidx[BGR * NGR];            // original local index
__device__ int    g_cellstart[BGR * NCELL + 1]; // absolute offsets (+sentinel)

__device__ __forceinline__ int clamp_x(float v) {
    int c = __float2int_rd(v * 0.1f);            // /10
    return min(NCX - 1, max(0, c));
}
__device__ __forceinline__ int clamp_yz(float v) {
    int c = __float2int_rd(v * 0.05f);           // /20
    return min(NCYZ - 1, max(0, c));
}

// ---- fused build: one CTA per graph, warp-shuffle scan (R7, kept) --------

__global__ __launch_bounds__(BT) void k_build(const float* __restrict__ pos) {
    __shared__ int s_cnt[NCELL];
    __shared__ int s_woff[BT / 32];   // 16 per-warp scan offsets
    __shared__ int s_cur[NCELL];

    const int b    = blockIdx.x;
    const int t    = threadIdx.x;
    const int warp = t >> 5;
    const int lane = t & 31;
    const unsigned FULL = 0xffffffffu;
    const float* gp = pos + (size_t)b * NGR * 3;

    for (int i = t; i < NCELL; i += BT) s_cnt[i] = 0;
    __syncthreads();

    // Phase 1: load nodes, compute cell ids, shared histogram.
    float px[NPT], py[NPT], pz[NPT];
    int   cid[NPT];
    #pragma unroll
    for (int k = 0; k < NPT; ++k) {
        int n = t + k * BT;
        px[k] = gp[3 * n + 0];
        py[k] = gp[3 * n + 1];
        pz[k] = gp[3 * n + 2];
        cid[k] = (clamp_yz(pz[k]) * NCYZ + clamp_yz(py[k])) * NCX + clamp_x(px[k]);
        atomicAdd(&s_cnt[cid[k]], 1);
    }
    __syncthreads();

    // Phase 2: exclusive scan of 250 counters (warp shfl scans + 1 top scan).
    int v = (t < NCELL) ? s_cnt[t] : 0;
    int incl = v;
    #pragma unroll
    for (int d = 1; d < 32; d <<= 1) {
        int u = __shfl_up_sync(FULL, incl, d);
        if (lane >= d) incl += u;
    }
    if (lane == 31) s_woff[warp] = incl;
    __syncthreads();
    if (warp == 0 && lane < BT / 32) {
        int w = s_woff[lane];
        int iw = w;
        #pragma unroll
        for (int d = 1; d < BT / 32; d <<= 1) {
            int u = __shfl_up_sync(0x0000ffffu, iw, d);
            if (lane >= d) iw += u;
        }
        s_woff[lane] = iw - w;   // exclusive warp offset
    }
    __syncthreads();
    if (t < NCELL) {
        int excl = incl - v + s_woff[warp];
        s_cur[t] = excl;
        g_cellstart[b * NCELL + t] = b * NGR + excl;
    }
    if (b == 0 && t == 0) g_cellstart[BGR * NCELL] = BGR * NGR;
    __syncthreads();

    // Phase 3: scatter via shared atomic cursors.
    const int base = b * NGR;
    #pragma unroll
    for (int k = 0; k < NPT; ++k) {
        int slot = base + atomicAdd(&s_cur[cid[k]], 1);
        float sq = __fadd_rn(__fadd_rn(__fmul_rn(px[k], px[k]),
                                       __fmul_rn(py[k], py[k])),
                             __fmul_rn(pz[k], pz[k]));
        g_sorted[slot] = make_float4(px[k], py[k], pz[k], sq);
        g_sidx[slot]   = t + k * BT;
    }
}

// ---- search: one warp per query, 32-bit distributed top-K (R6, kept) -----

__global__ __launch_bounds__(TPB) void k_search(
    const float* __restrict__ pos, float* __restrict__ out, int M)
{
    const int b    = blockIdx.y;
    const int warp = threadIdx.x >> 5;
    const int lane = threadIdx.x & 31;
    const unsigned FULL = 0xffffffffu;

    const int n = blockIdx.x * QPB + warp;
    const float* gp = pos + (size_t)b * NGR * 3;
    float qx = gp[3 * n + 0], qy = gp[3 * n + 1], qz = gp[3 * n + 2];
    float qw = __fadd_rn(__fadd_rn(__fmul_rn(qx, qx), __fmul_rn(qy, qy)),
                         __fmul_rn(qz, qz));

    const int x0 = clamp_x(qx - 10.01f),  x1 = clamp_x(qx + 10.01f);
    const int y0 = clamp_yz(qy - 10.01f), y1 = clamp_yz(qy + 10.01f);
    const int z0 = clamp_yz(qz - 10.01f), z1 = clamp_yz(qz + 10.01f);

    const float INF = __int_as_float(0x7f800000);
    float kd = INF;   // lane l holds l-th smallest (dist, idx)
    int   ki = -1;

    for (int cz = z0; cz <= z1; ++cz) {
        for (int cy = y0; cy <= y1; ++cy) {
            int rowbase = b * NCELL + (cz * NCYZ + cy) * NCX;
            int s = g_cellstart[rowbase + x0];
            int e = g_cellstart[rowbase + x1 + 1];  // contiguous x-run
            for (int t0 = s; t0 < e; t0 += 32) {
                int  t   = t0 + lane;
                bool act = t < e;
                float4 c = act ? g_sorted[t] : make_float4(0.f, 0.f, 0.f, 1e30f);
                // Reference-rounded GEMM-form d2 (no FMA, fixed association).
                float m1 = __fmul_rn(qx, c.x);
                float m2 = __fmul_rn(qy, c.y);
                float m3 = __fmul_rn(qz, c.z);
                float dote = __fadd_rn(__fadd_rn(m1, m2), m3);
                float tt   = __fadd_rn(qw, c.w);
                float d2   = __fsub_rn(tt, __fmul_rn(2.0f, dote));
                float de = INF;
                int   jl = n;  // self => excluded
                if (act && d2 <= 100.001f) {
                    de = __fsqrt_rn(fmaxf(d2, 0.0f));
                    jl = g_sidx[t];
                }
                unsigned emask = __ballot_sync(FULL, (de <= 10.0f) && (jl != n));
                while (emask) {
                    int src = __ffs(emask) - 1;
                    emask &= emask - 1;
                    float d  = __shfl_sync(FULL, de, src);
                    int   jj = __shfl_sync(FULL, jl, src);
                    // entries strictly before (d,jj) lexicographically stay put
                    int p = __popc(__ballot_sync(FULL,
                                (kd < d) || (kd == d && ki < jj)));
                    float sd = __shfl_up_sync(FULL, kd, 1);
                    int   si = __shfl_up_sync(FULL, ki, 1);
                    if (p < 32) {
                        if (lane == p)     { kd = d;  ki = jj; }
                        else if (lane > p) { kd = sd; ki = si; }
                    }
                }
            }
        }
    }

    // Emit: lane l writes slot l. Invalid -> zeros.
    const int  g    = b * NGR + n;
    const long base = (long)g * KNB;
    float* rowp = out;
    float* colp = out + (long)M;
    float* wp   = out + 2L * (long)M;
    float* vp   = out + 3L * (long)M;

    float rv = 0.0f, cv = 0.0f, wv = 0.0f, vv = 0.0f;
    if (kd < INF) {
        float cxp = gp[3 * ki + 0], cyp = gp[3 * ki + 1], czp = gp[3 * ki + 2];
        float dx = __fsub_rn(qx, cxp);
        float dy = __fsub_rn(qy, cyp);
        float dz = __fsub_rn(qz, czp);
        float ss = __fadd_rn(__fadd_rn(__fmul_rn(dx, dx), __fmul_rn(dy, dy)),
                             __fmul_rn(dz, dz));
        wv = __fsqrt_rn(ss);
        rv = (float)g;
        cv = (float)(b * NGR + ki);
        vv = 1.0f;
    }
    rowp[base + lane] = rv;
    colp[base + lane] = cv;
    wp[base + lane]   = wv;
    vp[base + lane]   = vv;
}

// ---- launch --------------------------------------------------------------

extern "C" void kernel_launch(void* const* d_in, const int* in_sizes, int n_in,
                              void* d_out, int out_size) {
    const float* pos = (const float*)d_in[0];
    (void)in_sizes; (void)n_in;
    float* out = (float*)d_out;
    int M = out_size / 4;

    k_build<<<BGR, BT>>>(pos);
    dim3 grid(NGR / QPB, BGR, 1);
    k_search<<<grid, TPB>>>(pos, out, M);
}